// round 7
// baseline (speedup 1.0000x reference)
#include <cuda_runtime.h>
#include <stdint.h>
#include <math.h>

#define NB 64
#define NH 1024
#define NV 32000
#define NT 31
#define NBLK 125   // gemmF blocks (32000/256)

// -------- device scratch --------
__device__ float g_W1p[512 * 4096];    // gate-interleaved Wx1
__device__ float g_W2p[1024 * 4096];   // gate-interleaved Wx2+Wh2
__device__ float g_h0[NB * NH];
__device__ float g_h1[NB * NH];
__device__ float g_c[NB * NH];
__device__ float4 g_pm[NT * NBLK * NB];   // per-block softmax partials (m,S,T)
__device__ float4 g_pa[NT * NBLK * NB];   // per-block argmax partials (best, idx, l)

__device__ __forceinline__ float negInf() { return __int_as_float(0xff800000); }

// ---- packed f32x2 FMA (sm_103a): two independent rn-FMAs per instruction ----
__device__ __forceinline__ unsigned long long pk2(float x) {
    unsigned long long r;
    asm("mov.b64 %0, {%1, %1};" : "=l"(r) : "f"(x));
    return r;
}
__device__ __forceinline__ void fma2(unsigned long long& c, unsigned long long a,
                                     unsigned long long b) {
    asm("fma.rn.f32x2 %0, %1, %2, %0;" : "+l"(c) : "l"(a), "l"(b));
}
__device__ __forceinline__ float lo32(unsigned long long v) {
    return __uint_as_float((unsigned)v);
}
__device__ __forceinline__ float hi32(unsigned long long v) {
    return __uint_as_float((unsigned)(v >> 32));
}

// exact JAX threefry2x32 (20 rounds)
__device__ __forceinline__ void tf2x32(uint32_t k0, uint32_t k1,
                                       uint32_t x0, uint32_t x1,
                                       uint32_t& o0, uint32_t& o1) {
    uint32_t k2 = k0 ^ k1 ^ 0x1BD11BDAu;
    x0 += k0; x1 += k1;
#define TFR(r) { x0 += x1; x1 = (x1 << (r)) | (x1 >> (32 - (r))); x1 ^= x0; }
    TFR(13) TFR(15) TFR(26) TFR(6)
    x0 += k1; x1 += k2 + 1u;
    TFR(17) TFR(29) TFR(16) TFR(24)
    x0 += k2; x1 += k0 + 2u;
    TFR(13) TFR(15) TFR(26) TFR(6)
    x0 += k0; x1 += k1 + 3u;
    TFR(17) TFR(29) TFR(16) TFR(24)
    x0 += k1; x1 += k2 + 4u;
    TFR(13) TFR(15) TFR(26) TFR(6)
    x0 += k2; x1 += k0 + 5u;
#undef TFR
    o0 = x0; o1 = x1;
}

__device__ __forceinline__ float u01(uint32_t b) {
    float f = __uint_as_float((b >> 9) | 0x3f800000u) - 1.0f;
    return fmaxf(f, 1.17549435e-38f);
}

__device__ __forceinline__ void softmerge(float& m, float& S, float& T,
                                          float m2, float S2, float T2) {
    if (S2 == 0.f) return;
    if (S == 0.f) { m = m2; S = S2; T = T2; return; }
    if (m2 > m) {
        float t;
        t = m; m = m2; m2 = t;
        t = S; S = S2; S2 = t;
        t = T; T = T2; T2 = t;
    }
    float e = expf(m2 - m);
    S += S2 * e;
    T += (T2 + (m2 - m) * S2) * e;
}

__global__ void k_init(float* __restrict__ out) {
    int i = blockIdx.x * blockDim.x + threadIdx.x;
    if (i < NB * NH) g_c[i] = 0.f;
    if (i < 3 * NB * 2 * NT) out[i] = 0.f;
}

// Gate-interleave permutation: Wp[k][4j+q] = W[k][q*1024+j]
__global__ void k_prep(const float* __restrict__ Wx1, const float* __restrict__ Wx2,
                       const float* __restrict__ Wh2) {
    int idx = blockIdx.x * blockDim.x + threadIdx.x;   // < 1024*4096
    int k = idx >> 12, col = idx & 4095;
    int j = col >> 2, q = col & 3;
    int src = (k << 12) + (q << 10) + j;
    g_W2p[idx] = Wx2[src] + Wh2[src];
    if (k < 512) g_W1p[idx] = Wx1[src];
}

// Fused gate GEMM + LSTM pointwise.
// z(64 x 4096) = A(64 x K) @ Wp(K x 4096) + bias(permuted access), then
// c' = sig(f)*c + sig(i)*g ; h' = sig(o)*c'  (gate order i,f,g,o; linear act.)
__global__ __launch_bounds__(256) void gemmG(const float* __restrict__ A,
                                             const float* __restrict__ W,
                                             const float* __restrict__ bias,
                                             float* __restrict__ hout,
                                             int K) {
    __shared__ float As[16][64];
    __shared__ float Bs[16][32];
    const int tid = threadIdx.x;
    const int row = tid & 63;
    const int jj  = tid >> 6;              // 0..3
    const int j0  = blockIdx.x * 8;        // 8 j-states per block
    const int c0  = blockIdx.x * 32;       // 32 permuted cols per block
    const int ar = tid >> 2, ak = (tid & 3) * 4;

    unsigned long long aif0 = 0, ago0 = 0, aif1 = 0, ago1 = 0;

    // prefetch chunk 0
    float4 pa = *(const float4*)(A + ar * K + ak);
    float4 pb;
    int bk = tid >> 3, bc = (tid & 7) * 4;
    if (tid < 128) pb = *(const float4*)(W + (size_t)bk * 4096 + c0 + bc);

    for (int k0 = 0; k0 < K; k0 += 16) {
        As[ak + 0][ar] = pa.x; As[ak + 1][ar] = pa.y;
        As[ak + 2][ar] = pa.z; As[ak + 3][ar] = pa.w;
        if (tid < 128) *(float4*)&Bs[bk][bc] = pb;
        __syncthreads();
        if (k0 + 16 < K) {
            pa = *(const float4*)(A + ar * K + k0 + 16 + ak);
            if (tid < 128)
                pb = *(const float4*)(W + (size_t)(k0 + 16 + bk) * 4096 + c0 + bc);
        }
#pragma unroll
        for (int k = 0; k < 16; k++) {
            unsigned long long ap = pk2(As[k][row]);
            ulonglong2 bA = *(const ulonglong2*)&Bs[k][jj * 4];
            ulonglong2 bB = *(const ulonglong2*)&Bs[k][(jj + 4) * 4];
            fma2(aif0, ap, bA.x); fma2(ago0, ap, bA.y);
            fma2(aif1, ap, bB.x); fma2(ago1, ap, bB.y);
        }
        __syncthreads();
    }

#pragma unroll
    for (int cell = 0; cell < 2; cell++) {
        int j = j0 + jj + cell * 4;
        unsigned long long aif = cell ? aif1 : aif0;
        unsigned long long ago = cell ? ago1 : ago0;
        float zi = __fadd_rn(lo32(aif), bias[j]);
        float zf = __fadd_rn(hi32(aif), bias[1024 + j]);
        float zg = __fadd_rn(lo32(ago), bias[2048 + j]);
        float zo = __fadd_rn(hi32(ago), bias[3072 + j]);
        float si = 1.f / (1.f + expf(-zi));
        float sf = 1.f / (1.f + expf(-zf));
        float so = 1.f / (1.f + expf(-zo));
        int ci = row * NH + j;
        float cn = __fadd_rn(__fmul_rn(sf, g_c[ci]), __fmul_rn(si, zg));
        g_c[ci] = cn;
        hout[ci] = __fmul_rn(so, cn);
    }
}

// Fused logits GEMM + softmax partials + gumbel-argmax sampling.
// C(64 x 32000) = A(64 x 1024) @ Wd + bd, never materialized: each block
// (64 x 256 slice) reduces its slice to per-row (m,S,T) and best-of (l+g).
// Threefry is partitionable-mode (XOR-fold), exact; gumbel double-log only
// for filter survivors (identical formula to the passing R6 kernel).
__global__ __launch_bounds__(256) void gemmF(const float* __restrict__ A,
                                             const float* __restrict__ B,
                                             const float* __restrict__ bias,
                                             int t) {
    __shared__ float As[16][64];
    __shared__ float Bs[16][256];
    __shared__ float red[8][8];
    const int tid = threadIdx.x;
    const int rowg = tid >> 6;        // 0..3  (16 rows each)
    const int colg = tid & 63;        // 0..63 (4 cols each)
    const int n0 = blockIdx.x * 256;
    const int w = tid >> 5, lane = tid & 31;
    const int ar = tid >> 2, ak = (tid & 3) * 4;
    const int bk = tid >> 4, bc = (tid & 15) * 16;

    unsigned long long acc[8][4];
#pragma unroll
    for (int p = 0; p < 8; p++)
#pragma unroll
        for (int c = 0; c < 4; c++) acc[p][c] = 0ull;

    float4 pa = *(const float4*)(A + ar * NH + ak);
    float4 pb[4];
#pragma unroll
    for (int j = 0; j < 4; j++)
        pb[j] = *(const float4*)(B + (size_t)bk * NV + n0 + bc + j * 4);

    for (int k0 = 0; k0 < NH; k0 += 16) {
        As[ak + 0][ar] = pa.x; As[ak + 1][ar] = pa.y;
        As[ak + 2][ar] = pa.z; As[ak + 3][ar] = pa.w;
#pragma unroll
        for (int j = 0; j < 4; j++)
            *(float4*)&Bs[bk][bc + j * 4] = pb[j];
        __syncthreads();
        if (k0 + 16 < NH) {
            pa = *(const float4*)(A + ar * NH + k0 + 16 + ak);
#pragma unroll
            for (int j = 0; j < 4; j++)
                pb[j] = *(const float4*)(B + (size_t)(k0 + 16 + bk) * NV + n0 + bc + j * 4);
        }
#pragma unroll
        for (int k = 0; k < 16; k++) {
            ulonglong2 pAB = *(const ulonglong2*)&As[k][rowg * 16];
            ulonglong2 pCD = *(const ulonglong2*)&As[k][rowg * 16 + 4];
            ulonglong2 pEF = *(const ulonglong2*)&As[k][rowg * 16 + 8];
            ulonglong2 pGH = *(const ulonglong2*)&As[k][rowg * 16 + 12];
            float4 bv = *(const float4*)&Bs[k][colg * 4];
            unsigned long long b0 = pk2(bv.x), b1 = pk2(bv.y);
            unsigned long long b2 = pk2(bv.z), b3 = pk2(bv.w);
            fma2(acc[0][0], pAB.x, b0); fma2(acc[0][1], pAB.x, b1);
            fma2(acc[0][2], pAB.x, b2); fma2(acc[0][3], pAB.x, b3);
            fma2(acc[1][0], pAB.y, b0); fma2(acc[1][1], pAB.y, b1);
            fma2(acc[1][2], pAB.y, b2); fma2(acc[1][3], pAB.y, b3);
            fma2(acc[2][0], pCD.x, b0); fma2(acc[2][1], pCD.x, b1);
            fma2(acc[2][2], pCD.x, b2); fma2(acc[2][3], pCD.x, b3);
            fma2(acc[3][0], pCD.y, b0); fma2(acc[3][1], pCD.y, b1);
            fma2(acc[3][2], pCD.y, b2); fma2(acc[3][3], pCD.y, b3);
            fma2(acc[4][0], pEF.x, b0); fma2(acc[4][1], pEF.x, b1);
            fma2(acc[4][2], pEF.x, b2); fma2(acc[4][3], pEF.x, b3);
            fma2(acc[5][0], pEF.y, b0); fma2(acc[5][1], pEF.y, b1);
            fma2(acc[5][2], pEF.y, b2); fma2(acc[5][3], pEF.y, b3);
            fma2(acc[6][0], pGH.x, b0); fma2(acc[6][1], pGH.x, b1);
            fma2(acc[6][2], pGH.x, b2); fma2(acc[6][3], pGH.x, b3);
            fma2(acc[7][0], pGH.y, b0); fma2(acc[7][1], pGH.y, b1);
            fma2(acc[7][2], pGH.y, b2); fma2(acc[7][3], pGH.y, b3);
        }
        __syncthreads();
    }

    // ---- epilogue: per-row softmax partial + gumbel argmax ----
    float bcol[4];
#pragma unroll
    for (int c = 0; c < 4; c++) bcol[c] = bias[n0 + colg * 4 + c];
    uint32_t kk0, kk1;
    tf2x32(0u, 1234u, 0u, (uint32_t)t, kk0, kk1);   // fold_in(key(1234), t)

    for (int i = 0; i < 16; i++) {
        int p = i >> 1;
        int rowAbs = rowg * 16 + i;
        float m = negInf(), S = 0.f, T = 0.f;
        float best = negInf(), bl = 0.f;
        int bidx = 0x7fffffff;
#pragma unroll
        for (int c = 0; c < 4; c++) {
            float l = __fadd_rn((i & 1) ? hi32(acc[p][c]) : lo32(acc[p][c]), bcol[c]);
            // online softmax
            if (S == 0.f) { m = l; S = 1.f; T = 0.f; }
            else if (l > m) {
                float e = expf(m - l);
                T = (T + (m - l) * S) * e;
                S = S * e + 1.f;
                m = l;
            } else {
                float d = l - m, e = expf(d);
                S += e; T += d * e;
            }
            // sampling candidate
            int v = n0 + colg * 4 + c;
            uint32_t o0, o1;
            tf2x32(kk0, kk1, 0u, (uint32_t)(rowAbs * NV + v), o0, o1);
            float u = u01(o0 ^ o1);
            float af = -__logf(u);                 // fast upper-bound path
            float sapp = l - __logf(af);
            if (sapp + 0.02f > best || af < 1e-4f) {
                float g = (float)(-log(-log((double)u)));   // exact (R6 formula)
                float s = __fadd_rn(l, g);
                if (s > best || (s == best && v < bidx)) { best = s; bidx = v; bl = l; }
            }
        }
        // warp reduce (lanes = different col groups, same rows)
        for (int o = 16; o; o >>= 1) {
            float m2 = __shfl_down_sync(0xffffffffu, m, o);
            float S2 = __shfl_down_sync(0xffffffffu, S, o);
            float T2 = __shfl_down_sync(0xffffffffu, T, o);
            softmerge(m, S, T, m2, S2, T2);
            float v2 = __shfl_down_sync(0xffffffffu, best, o);
            int   i2 = __shfl_down_sync(0xffffffffu, bidx, o);
            float l2 = __shfl_down_sync(0xffffffffu, bl, o);
            if (v2 > best || (v2 == best && i2 < bidx)) { best = v2; bidx = i2; bl = l2; }
        }
        if (lane == 0) {
            red[w][0] = m; red[w][1] = S; red[w][2] = T;
            red[w][3] = best; red[w][4] = __int_as_float(bidx); red[w][5] = bl;
        }
        __syncthreads();
        if ((w & 1) == 0 && lane == 0) {
            // merge with sibling warp (covers cols n0+128..255)
            softmerge(m, S, T, red[w + 1][0], red[w + 1][1], red[w + 1][2]);
            float v2 = red[w + 1][3]; int i2 = __float_as_int(red[w + 1][4]);
            float l2 = red[w + 1][5];
            if (v2 > best || (v2 == best && i2 < bidx)) { best = v2; bidx = i2; bl = l2; }
            int o = (t * NBLK + blockIdx.x) * NB + rowAbs;
            g_pm[o] = make_float4(m, S, T, 0.f);
            g_pa[o] = make_float4(best, (float)bidx, bl, 0.f);
        }
        __syncthreads();
    }
}

// Final merge over the 125 block partials, all 31 steps at once.
__global__ void k_fin(float* __restrict__ out) {
    int t = blockIdx.x;
    int tid = threadIdx.x, w = tid >> 5, lane = tid & 31;
    for (int row = w; row < NB; row += 8) {
        float m = negInf(), S = 0.f, T = 0.f;
        float best = negInf(), bl = 0.f;
        int bidx = 0x7fffffff;
        for (int b = lane; b < NBLK; b += 32) {
            int o = (t * NBLK + b) * NB + row;
            float4 pm = g_pm[o];
            softmerge(m, S, T, pm.x, pm.y, pm.z);
            float4 pa = g_pa[o];
            int i2 = (int)pa.y;
            if (pa.x > best || (pa.x == best && i2 < bidx)) {
                best = pa.x; bidx = i2; bl = pa.z;
            }
        }
        for (int o = 16; o; o >>= 1) {
            float m2 = __shfl_down_sync(0xffffffffu, m, o);
            float S2 = __shfl_down_sync(0xffffffffu, S, o);
            float T2 = __shfl_down_sync(0xffffffffu, T, o);
            softmerge(m, S, T, m2, S2, T2);
            float v2 = __shfl_down_sync(0xffffffffu, best, o);
            int   i2 = __shfl_down_sync(0xffffffffu, bidx, o);
            float l2 = __shfl_down_sync(0xffffffffu, bl, o);
            if (v2 > best || (v2 == best && i2 < bidx)) { best = v2; bidx = i2; bl = l2; }
        }
        if (lane == 0) {
            float lS = (float)log((double)S);
            out[2 * NB * 2 * NT + row * (2 * NT) + t] = lS - T / S;   // entropy
            out[row * (2 * NT) + t] = (float)bidx;                    // msg
            out[NB * 2 * NT + row * (2 * NT) + t] =
                __fadd_rn(__fadd_rn(bl, -m), -lS);                    // log_prob
        }
    }
}

__global__ void k_copyh(float* __restrict__ out, const float* __restrict__ h) {
    int i = blockIdx.x * blockDim.x + threadIdx.x;
    if (i < NB * NH) out[3 * NB * 2 * NT + i] = h[i];
}

extern "C" void kernel_launch(void* const* d_in, const int* in_sizes, int n_in,
                              void* d_out, int out_size) {
    // Size-based dispatch (robust to metadata ordering):
    const float *inp = 0, *Wx1 = 0, *Wd = 0, *bd = 0, *b1 = 0, *b2 = 0;
    const float* w4[3] = {0, 0, 0};
    int n4 = 0;
    for (int i = 0; i < n_in; i++) {
        const float* p = (const float*)d_in[i];
        switch (in_sizes[i]) {
            case 32768:    inp = p; break;
            case 2097152:  Wx1 = p; break;
            case 4194304:  if (n4 < 3) w4[n4++] = p; break;   // Wh1(unused), Wx2, Wh2
            case 32768000: Wd = p; break;
            case 32000:    bd = p; break;
            case 4096:     if (!b1) b1 = p; else b2 = p; break;
            default: break;
        }
    }
    float* out = (float*)d_out;

    void *pw1, *pw2, *ph0, *ph1;
    cudaGetSymbolAddress(&pw1, g_W1p);
    cudaGetSymbolAddress(&pw2, g_W2p);
    cudaGetSymbolAddress(&ph0, g_h0);
    cudaGetSymbolAddress(&ph1, g_h1);
    float* W1p = (float*)pw1;
    float* W2p = (float*)pw2;
    float* h0  = (float*)ph0;
    float* h1  = (float*)ph1;

    k_init<<<256, 256>>>(out);
    k_prep<<<16384, 256>>>(Wx1, w4[1], w4[2]);

    // encoder: one step, zero state -> h0
    gemmG<<<128, 256>>>(inp, W1p, b1, h0, 512);

    for (int t = 0; t < NT; t++) {
        const float* hin = (t & 1) ? h1 : h0;
        float* hnew      = (t & 1) ? h0 : h1;
        gemmG<<<128, 256>>>(hin, W2p, b2, hnew, NH);
        gemmF<<<NBLK, 256>>>(hnew, Wd, bd, t);
    }
    k_fin<<<NT, 256>>>(out);
    k_copyh<<<256, 256>>>(out, h1);
}

// round 8
// speedup vs baseline: 1.7668x; 1.7668x over previous
#include <cuda_runtime.h>
#include <stdint.h>
#include <math.h>

#define NB 64
#define NH 1024
#define NV 32000
#define NT 31
#define NBLK 125   // gemmF blocks (32000/256)

// -------- device scratch --------
__device__ float g_W1p[512 * 4096];    // gate-interleaved Wx1
__device__ float g_W2p[1024 * 4096];   // gate-interleaved Wx2+Wh2
__device__ float g_h0[NB * NH];
__device__ float g_h1[NB * NH];
__device__ float g_c[NB * NH];
__device__ float4 g_pm[NT * NBLK * NB];   // per-block softmax partials (m,S,T)
__device__ float4 g_pa[NT * NBLK * NB];   // per-block argmax partials (best, idx, l)

__device__ __forceinline__ float negInf() { return __int_as_float(0xff800000); }

// ---- packed f32x2 FMA (sm_103a): two independent rn-FMAs per instruction ----
__device__ __forceinline__ unsigned long long pk2(float x) {
    unsigned long long r;
    asm("mov.b64 %0, {%1, %1};" : "=l"(r) : "f"(x));
    return r;
}
__device__ __forceinline__ void fma2(unsigned long long& c, unsigned long long a,
                                     unsigned long long b) {
    asm("fma.rn.f32x2 %0, %1, %2, %0;" : "+l"(c) : "l"(a), "l"(b));
}
__device__ __forceinline__ float lo32(unsigned long long v) {
    return __uint_as_float((unsigned)v);
}
__device__ __forceinline__ float hi32(unsigned long long v) {
    return __uint_as_float((unsigned)(v >> 32));
}

// exact JAX threefry2x32 (20 rounds)
__device__ __forceinline__ void tf2x32(uint32_t k0, uint32_t k1,
                                       uint32_t x0, uint32_t x1,
                                       uint32_t& o0, uint32_t& o1) {
    uint32_t k2 = k0 ^ k1 ^ 0x1BD11BDAu;
    x0 += k0; x1 += k1;
#define TFR(r) { x0 += x1; x1 = (x1 << (r)) | (x1 >> (32 - (r))); x1 ^= x0; }
    TFR(13) TFR(15) TFR(26) TFR(6)
    x0 += k1; x1 += k2 + 1u;
    TFR(17) TFR(29) TFR(16) TFR(24)
    x0 += k2; x1 += k0 + 2u;
    TFR(13) TFR(15) TFR(26) TFR(6)
    x0 += k0; x1 += k1 + 3u;
    TFR(17) TFR(29) TFR(16) TFR(24)
    x0 += k1; x1 += k2 + 4u;
    TFR(13) TFR(15) TFR(26) TFR(6)
    x0 += k2; x1 += k0 + 5u;
#undef TFR
    o0 = x0; o1 = x1;
}

__device__ __forceinline__ float u01(uint32_t b) {
    float f = __uint_as_float((b >> 9) | 0x3f800000u) - 1.0f;
    return fmaxf(f, 1.17549435e-38f);
}

// exact gumbel increment (bit-identical to the passing R6/R7 formula)
__device__ __forceinline__ float exact_g(float u) {
    return (float)(-log(-log((double)u)));
}

__device__ __forceinline__ void softmerge(float& m, float& S, float& T,
                                          float m2, float S2, float T2) {
    if (S2 == 0.f) return;
    if (S == 0.f) { m = m2; S = S2; T = T2; return; }
    if (m2 > m) {
        float t;
        t = m; m = m2; m2 = t;
        t = S; S = S2; S2 = t;
        t = T; T = T2; T2 = t;
    }
    float e = expf(m2 - m);
    S += S2 * e;
    T += (T2 + (m2 - m) * S2) * e;
}

__global__ void k_init() {
    int i = blockIdx.x * blockDim.x + threadIdx.x;
    if (i < NB * NH) g_c[i] = 0.f;
}
__global__ void k_init2(float* __restrict__ out) {
    int i = blockIdx.x * blockDim.x + threadIdx.x;
    if (i < 3 * NB * 2 * NT) out[i] = 0.f;
}

// Gate-interleave permutation: Wp[k][4j+q] = W[k][q*1024+j]
__global__ void k_prep(const float* __restrict__ Wx1, const float* __restrict__ Wx2,
                       const float* __restrict__ Wh2) {
    int idx = blockIdx.x * blockDim.x + threadIdx.x;   // < 1024*4096
    int k = idx >> 12, col = idx & 4095;
    int j = col >> 2, q = col & 3;
    int src = (k << 12) + (q << 10) + j;
    g_W2p[idx] = Wx2[src] + Wh2[src];
    if (k < 512) g_W1p[idx] = Wx1[src];
}

// Fused gate GEMM + LSTM pointwise, depth-2 register prefetch (hides DRAM lat).
__global__ __launch_bounds__(256) void gemmG(const float* __restrict__ A,
                                             const float* __restrict__ W,
                                             const float* __restrict__ bias,
                                             float* __restrict__ hout,
                                             int K) {
    __shared__ float As[16][64];
    __shared__ float Bs[16][32];
    const int tid = threadIdx.x;
    const int row = tid & 63;
    const int jj  = tid >> 6;              // 0..3
    const int j0  = blockIdx.x * 8;        // 8 j-states per block
    const int c0  = blockIdx.x * 32;       // 32 permuted cols per block
    const int ar = tid >> 2, ak = (tid & 3) * 4;
    const int bk = tid >> 3, bc = (tid & 7) * 4;

    unsigned long long aif0 = 0, ago0 = 0, aif1 = 0, ago1 = 0;

    // depth-2 prefetch: chunks 0 and 16 in registers
    float4 pa0 = *(const float4*)(A + ar * K + ak);
    float4 pa1 = *(const float4*)(A + ar * K + 16 + ak);
    float4 pb0, pb1;
    if (tid < 128) {
        pb0 = *(const float4*)(W + (size_t)bk * 4096 + c0 + bc);
        pb1 = *(const float4*)(W + (size_t)(16 + bk) * 4096 + c0 + bc);
    }

    for (int k0 = 0; k0 < K; k0 += 16) {
        As[ak + 0][ar] = pa0.x; As[ak + 1][ar] = pa0.y;
        As[ak + 2][ar] = pa0.z; As[ak + 3][ar] = pa0.w;
        if (tid < 128) *(float4*)&Bs[bk][bc] = pb0;
        __syncthreads();
        pa0 = pa1;
        if (tid < 128) pb0 = pb1;
        if (k0 + 32 < K) {
            pa1 = *(const float4*)(A + ar * K + k0 + 32 + ak);
            if (tid < 128)
                pb1 = *(const float4*)(W + (size_t)(k0 + 32 + bk) * 4096 + c0 + bc);
        }
#pragma unroll
        for (int k = 0; k < 16; k++) {
            unsigned long long ap = pk2(As[k][row]);
            ulonglong2 bA = *(const ulonglong2*)&Bs[k][jj * 4];
            ulonglong2 bB = *(const ulonglong2*)&Bs[k][(jj + 4) * 4];
            fma2(aif0, ap, bA.x); fma2(ago0, ap, bA.y);
            fma2(aif1, ap, bB.x); fma2(ago1, ap, bB.y);
        }
        __syncthreads();
    }

#pragma unroll
    for (int cell = 0; cell < 2; cell++) {
        int j = j0 + jj + cell * 4;
        unsigned long long aif = cell ? aif1 : aif0;
        unsigned long long ago = cell ? ago1 : ago0;
        float zi = __fadd_rn(lo32(aif), bias[j]);
        float zf = __fadd_rn(hi32(aif), bias[1024 + j]);
        float zg = __fadd_rn(lo32(ago), bias[2048 + j]);
        float zo = __fadd_rn(hi32(ago), bias[3072 + j]);
        float si = 1.f / (1.f + expf(-zi));
        float sf = 1.f / (1.f + expf(-zf));
        float so = 1.f / (1.f + expf(-zo));
        int ci = row * NH + j;
        float cn = __fadd_rn(__fmul_rn(sf, g_c[ci]), __fmul_rn(si, zg));
        g_c[ci] = cn;
        hout[ci] = __fmul_rn(so, cn);
    }
}

// Fused logits GEMM + softmax partials + gumbel-argmax sampling.
// Epilogue: pass A = fast fp32 approx scores (tail af<1e-4 exact immediately),
// row-max reduce; pass B = exact fp64 gumbel only within 4e-3 margin of row-max.
__global__ __launch_bounds__(256) void gemmF(const float* __restrict__ A,
                                             const float* __restrict__ B,
                                             const float* __restrict__ bias,
                                             int t) {
    __shared__ float As[16][64];
    __shared__ float Bs[16][256];
    __shared__ float red[8][8];
    const int tid = threadIdx.x;
    const int rowg = tid >> 6;        // 0..3  (16 rows each)
    const int colg = tid & 63;        // 0..63 (4 cols each)
    const int n0 = blockIdx.x * 256;
    const int w = tid >> 5, lane = tid & 31;
    const int ar = tid >> 2, ak = (tid & 3) * 4;
    const int bk = tid >> 4, bc = (tid & 15) * 16;

    unsigned long long acc[8][4];
#pragma unroll
    for (int p = 0; p < 8; p++)
#pragma unroll
        for (int c = 0; c < 4; c++) acc[p][c] = 0ull;

    float4 pa = *(const float4*)(A + ar * NH + ak);
    float4 pb[4];
#pragma unroll
    for (int j = 0; j < 4; j++)
        pb[j] = *(const float4*)(B + (size_t)bk * NV + n0 + bc + j * 4);

    for (int k0 = 0; k0 < NH; k0 += 16) {
        As[ak + 0][ar] = pa.x; As[ak + 1][ar] = pa.y;
        As[ak + 2][ar] = pa.z; As[ak + 3][ar] = pa.w;
#pragma unroll
        for (int j = 0; j < 4; j++)
            *(float4*)&Bs[bk][bc + j * 4] = pb[j];
        __syncthreads();
        if (k0 + 16 < NH) {
            pa = *(const float4*)(A + ar * NH + k0 + 16 + ak);
#pragma unroll
            for (int j = 0; j < 4; j++)
                pb[j] = *(const float4*)(B + (size_t)(k0 + 16 + bk) * NV + n0 + bc + j * 4);
        }
#pragma unroll
        for (int k = 0; k < 16; k++) {
            ulonglong2 pAB = *(const ulonglong2*)&As[k][rowg * 16];
            ulonglong2 pCD = *(const ulonglong2*)&As[k][rowg * 16 + 4];
            ulonglong2 pEF = *(const ulonglong2*)&As[k][rowg * 16 + 8];
            ulonglong2 pGH = *(const ulonglong2*)&As[k][rowg * 16 + 12];
            float4 bv = *(const float4*)&Bs[k][colg * 4];
            unsigned long long b0 = pk2(bv.x), b1 = pk2(bv.y);
            unsigned long long b2 = pk2(bv.z), b3 = pk2(bv.w);
            fma2(acc[0][0], pAB.x, b0); fma2(acc[0][1], pAB.x, b1);
            fma2(acc[0][2], pAB.x, b2); fma2(acc[0][3], pAB.x, b3);
            fma2(acc[1][0], pAB.y, b0); fma2(acc[1][1], pAB.y, b1);
            fma2(acc[1][2], pAB.y, b2); fma2(acc[1][3], pAB.y, b3);
            fma2(acc[2][0], pCD.x, b0); fma2(acc[2][1], pCD.x, b1);
            fma2(acc[2][2], pCD.x, b2); fma2(acc[2][3], pCD.x, b3);
            fma2(acc[3][0], pCD.y, b0); fma2(acc[3][1], pCD.y, b1);
            fma2(acc[3][2], pCD.y, b2); fma2(acc[3][3], pCD.y, b3);
            fma2(acc[4][0], pEF.x, b0); fma2(acc[4][1], pEF.x, b1);
            fma2(acc[4][2], pEF.x, b2); fma2(acc[4][3], pEF.x, b3);
            fma2(acc[5][0], pEF.y, b0); fma2(acc[5][1], pEF.y, b1);
            fma2(acc[5][2], pEF.y, b2); fma2(acc[5][3], pEF.y, b3);
            fma2(acc[6][0], pGH.x, b0); fma2(acc[6][1], pGH.x, b1);
            fma2(acc[6][2], pGH.x, b2); fma2(acc[6][3], pGH.x, b3);
            fma2(acc[7][0], pGH.y, b0); fma2(acc[7][1], pGH.y, b1);
            fma2(acc[7][2], pGH.y, b2); fma2(acc[7][3], pGH.y, b3);
        }
        __syncthreads();
    }

    // ---- epilogue ----
    float bcol[4];
#pragma unroll
    for (int c = 0; c < 4; c++) bcol[c] = bias[n0 + colg * 4 + c];
    uint32_t kk0, kk1;
    tf2x32(0u, 1234u, 0u, (uint32_t)t, kk0, kk1);   // fold_in(key(1234), t)

    for (int i = 0; i < 16; i++) {
        int p = i >> 1;
        int rowAbs = rowg * 16 + i;
        float m = negInf(), S = 0.f, T = 0.f;

        // pass A: approx scores (tail exact), thread-local row max
        float ll[4], uu[4], sv[4];
        uint32_t approxMask = 0;
        float rb = negInf();
#pragma unroll
        for (int c = 0; c < 4; c++) {
            float l = __fadd_rn((i & 1) ? hi32(acc[p][c]) : lo32(acc[p][c]), bcol[c]);
            ll[c] = l;
            // online softmax (unchanged path)
            if (S == 0.f) { m = l; S = 1.f; T = 0.f; }
            else if (l > m) {
                float e = expf(m - l);
                T = (T + (m - l) * S) * e;
                S = S * e + 1.f;
                m = l;
            } else {
                float d = l - m, e = expf(d);
                S += e; T += d * e;
            }
            int v = n0 + colg * 4 + c;
            uint32_t o0, o1;
            tf2x32(kk0, kk1, 0u, (uint32_t)(rowAbs * NV + v), o0, o1);
            float u = u01(o0 ^ o1);
            uu[c] = u;
            float af = -__logf(u);
            float s;
            if (af < 1e-4f) {
                s = __fadd_rn(l, exact_g(u));       // exact now (tail, likely winner)
            } else {
                s = l - __logf(af);                 // fast approx
                approxMask |= (1u << c);
            }
            sv[c] = s;
            rb = fmaxf(rb, s);
        }
        // row max over 64 threads (warp allreduce + pair-warp via smem)
        for (int o = 16; o; o >>= 1)
            rb = fmaxf(rb, __shfl_xor_sync(0xffffffffu, rb, o));
        if (lane == 0) red[w][6] = rb;
        __syncthreads();
        rb = fmaxf(rb, red[w ^ 1][6]);
        float thresh = rb - 4e-3f;

        // pass B: exact-evaluate only margin survivors, exact reduce
        float best = negInf(), bl = 0.f;
        int bidx = 0x7fffffff;
#pragma unroll
        for (int c = 0; c < 4; c++) {
            float s;
            if (approxMask & (1u << c)) {
                if (sv[c] < thresh) continue;
                s = __fadd_rn(ll[c], exact_g(uu[c]));
            } else {
                s = sv[c];                          // already exact
                if (s < thresh) continue;
            }
            int v = n0 + colg * 4 + c;
            if (s > best || (s == best && v < bidx)) { best = s; bidx = v; bl = ll[c]; }
        }
        // warp reduce (softmax partials + exact argmax)
        for (int o = 16; o; o >>= 1) {
            float m2 = __shfl_down_sync(0xffffffffu, m, o);
            float S2 = __shfl_down_sync(0xffffffffu, S, o);
            float T2 = __shfl_down_sync(0xffffffffu, T, o);
            softmerge(m, S, T, m2, S2, T2);
            float v2 = __shfl_down_sync(0xffffffffu, best, o);
            int   i2 = __shfl_down_sync(0xffffffffu, bidx, o);
            float l2 = __shfl_down_sync(0xffffffffu, bl, o);
            if (v2 > best || (v2 == best && i2 < bidx)) { best = v2; bidx = i2; bl = l2; }
        }
        __syncthreads();   // protect red[][6] before reuse of red[w][0..5]
        if (lane == 0) {
            red[w][0] = m; red[w][1] = S; red[w][2] = T;
            red[w][3] = best; red[w][4] = __int_as_float(bidx); red[w][5] = bl;
        }
        __syncthreads();
        if ((w & 1) == 0 && lane == 0) {
            softmerge(m, S, T, red[w + 1][0], red[w + 1][1], red[w + 1][2]);
            float v2 = red[w + 1][3]; int i2 = __float_as_int(red[w + 1][4]);
            float l2 = red[w + 1][5];
            if (v2 > best || (v2 == best && i2 < bidx)) { best = v2; bidx = i2; bl = l2; }
            int o = (t * NBLK + blockIdx.x) * NB + rowAbs;
            g_pm[o] = make_float4(m, S, T, 0.f);
            g_pa[o] = make_float4(best, (float)bidx, bl, 0.f);
        }
        __syncthreads();
    }
}

// Final merge over the 125 block partials, all 31 steps at once.
__global__ void k_fin(float* __restrict__ out) {
    int t = blockIdx.x;
    int tid = threadIdx.x, w = tid >> 5, lane = tid & 31;
    for (int row = w; row < NB; row += 8) {
        float m = negInf(), S = 0.f, T = 0.f;
        float best = negInf(), bl = 0.f;
        int bidx = 0x7fffffff;
        for (int b = lane; b < NBLK; b += 32) {
            int o = (t * NBLK + b) * NB + row;
            float4 pm = g_pm[o];
            softmerge(m, S, T, pm.x, pm.y, pm.z);
            float4 pa = g_pa[o];
            int i2 = (int)pa.y;
            if (pa.x > best || (pa.x == best && i2 < bidx)) {
                best = pa.x; bidx = i2; bl = pa.z;
            }
        }
        for (int o = 16; o; o >>= 1) {
            float m2 = __shfl_down_sync(0xffffffffu, m, o);
            float S2 = __shfl_down_sync(0xffffffffu, S, o);
            float T2 = __shfl_down_sync(0xffffffffu, T, o);
            softmerge(m, S, T, m2, S2, T2);
            float v2 = __shfl_down_sync(0xffffffffu, best, o);
            int   i2 = __shfl_down_sync(0xffffffffu, bidx, o);
            float l2 = __shfl_down_sync(0xffffffffu, bl, o);
            if (v2 > best || (v2 == best && i2 < bidx)) { best = v2; bidx = i2; bl = l2; }
        }
        if (lane == 0) {
            float lS = (float)log((double)S);
            out[2 * NB * 2 * NT + row * (2 * NT) + t] = lS - T / S;   // entropy
            out[row * (2 * NT) + t] = (float)bidx;                    // msg
            out[NB * 2 * NT + row * (2 * NT) + t] =
                __fadd_rn(__fadd_rn(bl, -m), -lS);                    // log_prob
        }
    }
}

__global__ void k_copyh(float* __restrict__ out, const float* __restrict__ h) {
    int i = blockIdx.x * blockDim.x + threadIdx.x;
    if (i < NB * NH) out[3 * NB * 2 * NT + i] = h[i];
}

extern "C" void kernel_launch(void* const* d_in, const int* in_sizes, int n_in,
                              void* d_out, int out_size) {
    // Size-based dispatch (robust to metadata ordering):
    const float *inp = 0, *Wx1 = 0, *Wd = 0, *bd = 0, *b1 = 0, *b2 = 0;
    const float* w4[3] = {0, 0, 0};
    int n4 = 0;
    for (int i = 0; i < n_in; i++) {
        const float* p = (const float*)d_in[i];
        switch (in_sizes[i]) {
            case 32768:    inp = p; break;
            case 2097152:  Wx1 = p; break;
            case 4194304:  if (n4 < 3) w4[n4++] = p; break;   // Wh1(unused), Wx2, Wh2
            case 32768000: Wd = p; break;
            case 32000:    bd = p; break;
            case 4096:     if (!b1) b1 = p; else b2 = p; break;
            default: break;
        }
    }
    float* out = (float*)d_out;

    void *pw1, *pw2, *ph0, *ph1;
    cudaGetSymbolAddress(&pw1, g_W1p);
    cudaGetSymbolAddress(&pw2, g_W2p);
    cudaGetSymbolAddress(&ph0, g_h0);
    cudaGetSymbolAddress(&ph1, g_h1);
    float* W1p = (float*)pw1;
    float* W2p = (float*)pw2;
    float* h0  = (float*)ph0;
    float* h1  = (float*)ph1;

    k_init<<<256, 256>>>();             // launch 0
    k_init2<<<48, 256>>>(out);          // launch 1
    k_prep<<<16384, 256>>>(Wx1, w4[1], w4[2]);   // launch 2

    // encoder: one step, zero state -> h0   (launch 3)
    gemmG<<<128, 256>>>(inp, W1p, b1, h0, 512);

    for (int t = 0; t < NT; t++) {
        const float* hin = (t & 1) ? h1 : h0;
        float* hnew      = (t & 1) ? h0 : h1;
        gemmG<<<128, 256>>>(hin, W2p, b2, hnew, NH);   // launch 4, 6, ...
        gemmF<<<NBLK, 256>>>(hnew, Wd, bd, t);         // launch 5 -> profiled
    }
    k_fin<<<NT, 256>>>(out);
    k_copyh<<<256, 256>>>(out, h1);
}

// round 10
// speedup vs baseline: 3.1741x; 1.7965x over previous
#include <cuda_runtime.h>
#include <stdint.h>
#include <math.h>

#define NB 64
#define NH 1024
#define NV 32000
#define NT 31
#define NBLK 125   // gemmF n-slices (32000/256)

// -------- device scratch --------
__device__ float g_W1p[512 * 4096];     // gate-interleaved Wx1
__device__ float g_W2p[1024 * 4096];    // gate-interleaved Wx2+Wh2
__device__ float g_hs[(NT + 1) * NB * NH];  // h after encoder (hs[0]) and each decoder step
__device__ float g_c[NB * NH];
__device__ float4 g_pm[NT * NBLK * NB];    // per-block softmax partials (m,S,T)
__device__ float4 g_pa[NT * NBLK * NB];    // per-block argmax partials (best, idx, l)

__device__ __forceinline__ float negInf() { return __int_as_float(0xff800000); }

// ---- packed f32x2 FMA (sm_103a): two independent rn-FMAs per instruction ----
__device__ __forceinline__ unsigned long long pk2(float x) {
    unsigned long long r;
    asm("mov.b64 %0, {%1, %1};" : "=l"(r) : "f"(x));
    return r;
}
__device__ __forceinline__ void fma2(unsigned long long& c, unsigned long long a,
                                     unsigned long long b) {
    asm("fma.rn.f32x2 %0, %1, %2, %0;" : "+l"(c) : "l"(a), "l"(b));
}
__device__ __forceinline__ float lo32(unsigned long long v) {
    return __uint_as_float((unsigned)v);
}
__device__ __forceinline__ float hi32(unsigned long long v) {
    return __uint_as_float((unsigned)(v >> 32));
}

// exact JAX threefry2x32 (20 rounds)
__device__ __forceinline__ void tf2x32(uint32_t k0, uint32_t k1,
                                       uint32_t x0, uint32_t x1,
                                       uint32_t& o0, uint32_t& o1) {
    uint32_t k2 = k0 ^ k1 ^ 0x1BD11BDAu;
    x0 += k0; x1 += k1;
#define TFR(r) { x0 += x1; x1 = (x1 << (r)) | (x1 >> (32 - (r))); x1 ^= x0; }
    TFR(13) TFR(15) TFR(26) TFR(6)
    x0 += k1; x1 += k2 + 1u;
    TFR(17) TFR(29) TFR(16) TFR(24)
    x0 += k2; x1 += k0 + 2u;
    TFR(13) TFR(15) TFR(26) TFR(6)
    x0 += k0; x1 += k1 + 3u;
    TFR(17) TFR(29) TFR(16) TFR(24)
    x0 += k1; x1 += k2 + 4u;
    TFR(13) TFR(15) TFR(26) TFR(6)
    x0 += k2; x1 += k0 + 5u;
#undef TFR
    o0 = x0; o1 = x1;
}

__device__ __forceinline__ float u01(uint32_t b) {
    float f = __uint_as_float((b >> 9) | 0x3f800000u) - 1.0f;
    return fmaxf(f, 1.17549435e-38f);
}

// exact gumbel increment (bit-identical to R6/R7/R8 formula)
__device__ __forceinline__ float exact_g(float u) {
    return (float)(-log(-log((double)u)));
}

__device__ __forceinline__ void softmerge(float& m, float& S, float& T,
                                          float m2, float S2, float T2) {
    if (S2 == 0.f) return;
    if (S == 0.f) { m = m2; S = S2; T = T2; return; }
    if (m2 > m) {
        float t;
        t = m; m = m2; m2 = t;
        t = S; S = S2; S2 = t;
        t = T; T = T2; T2 = t;
    }
    float e = expf(m2 - m);
    S += S2 * e;
    T += (T2 + (m2 - m) * S2) * e;
}

__global__ void k_init() {
    int i = blockIdx.x * blockDim.x + threadIdx.x;
    if (i < NB * NH) g_c[i] = 0.f;
}
__global__ void k_init2(float* __restrict__ out) {
    int i = blockIdx.x * blockDim.x + threadIdx.x;
    if (i < 3 * NB * 2 * NT) out[i] = 0.f;
}

// Gate-interleave permutation: Wp[k][4j+q] = W[k][q*1024+j]
__global__ void k_prep(const float* __restrict__ Wx1, const float* __restrict__ Wx2,
                       const float* __restrict__ Wh2) {
    int idx = blockIdx.x * blockDim.x + threadIdx.x;   // < 1024*4096
    int k = idx >> 12, col = idx & 4095;
    int j = col >> 2, q = col & 3;
    int src = (k << 12) + (q << 10) + j;
    g_W2p[idx] = Wx2[src] + Wh2[src];
    if (k < 512) g_W1p[idx] = Wx1[src];
}

// Fused gate GEMM + LSTM pointwise. 256 blocks x 4 states -> 2 blocks/SM,
// 4 warps/SMSP for latency hiding. One cell per thread (aif, ago packed).
__global__ __launch_bounds__(256, 2) void gemmG(const float* __restrict__ A,
                                                const float* __restrict__ W,
                                                const float* __restrict__ bias,
                                                float* __restrict__ hout,
                                                int K) {
    __shared__ float As[16][64];
    __shared__ float Bs[16][16];
    const int tid = threadIdx.x;
    const int row = tid & 63;
    const int jj  = tid >> 6;              // 0..3
    const int j0  = blockIdx.x * 4;        // 4 j-states per block
    const int c0  = blockIdx.x * 16;       // 16 permuted cols per block
    const int ar = tid >> 2, ak = (tid & 3) * 4;
    const int bk = tid >> 2, bc = (tid & 3) * 4;   // B staging (tid < 64)

    unsigned long long aif = 0, ago = 0;

    // depth-2 register prefetch
    float4 pa0 = *(const float4*)(A + ar * K + ak);
    float4 pa1 = *(const float4*)(A + ar * K + 16 + ak);
    float4 pb0, pb1;
    if (tid < 64) {
        pb0 = *(const float4*)(W + (size_t)bk * 4096 + c0 + bc);
        pb1 = *(const float4*)(W + (size_t)(16 + bk) * 4096 + c0 + bc);
    }

    for (int k0 = 0; k0 < K; k0 += 16) {
        As[ak + 0][ar] = pa0.x; As[ak + 1][ar] = pa0.y;
        As[ak + 2][ar] = pa0.z; As[ak + 3][ar] = pa0.w;
        if (tid < 64) *(float4*)&Bs[bk][bc] = pb0;
        __syncthreads();
        pa0 = pa1;
        if (tid < 64) pb0 = pb1;
        if (k0 + 32 < K) {
            pa1 = *(const float4*)(A + ar * K + k0 + 32 + ak);
            if (tid < 64)
                pb1 = *(const float4*)(W + (size_t)(k0 + 32 + bk) * 4096 + c0 + bc);
        }
#pragma unroll
        for (int k = 0; k < 16; k++) {
            unsigned long long ap = pk2(As[k][row]);
            ulonglong2 bA = *(const ulonglong2*)&Bs[k][jj * 4];
            fma2(aif, ap, bA.x);
            fma2(ago, ap, bA.y);
        }
        __syncthreads();
    }

    int j = j0 + jj;
    float zi = __fadd_rn(lo32(aif), bias[j]);
    float zf = __fadd_rn(hi32(aif), bias[1024 + j]);
    float zg = __fadd_rn(lo32(ago), bias[2048 + j]);
    float zo = __fadd_rn(hi32(ago), bias[3072 + j]);
    float si = 1.f / (1.f + expf(-zi));
    float sf = 1.f / (1.f + expf(-zf));
    float so = 1.f / (1.f + expf(-zo));
    int ci = row * NH + j;
    float cn = __fadd_rn(__fmul_rn(sf, g_c[ci]), __fmul_rn(si, zg));
    g_c[ci] = cn;
    hout[ci] = __fmul_rn(so, cn);
}

// ALL 31 steps' logits GEMM + softmax partials + gumbel sampling in one grid.
// blockIdx.x = t (31), blockIdx.y = n-slice (125). Same-wave blocks share t
// variety but the same few n-slices -> Wd L2 reuse. 13 waves hide all stalls.
__global__ __launch_bounds__(256, 2) void gemmF(const float* __restrict__ hs,
                                                const float* __restrict__ B,
                                                const float* __restrict__ bias) {
    __shared__ float As[16][64];
    __shared__ float Bs[16][256];
    __shared__ float red[8][8];
    const int t = blockIdx.x;
    const float* A = hs + (size_t)(t + 1) * NB * NH;
    const int tid = threadIdx.x;
    const int rowg = tid >> 6;        // 0..3  (16 rows each)
    const int colg = tid & 63;        // 0..63 (4 cols each)
    const int n0 = blockIdx.y * 256;
    const int w = tid >> 5, lane = tid & 31;
    const int ar = tid >> 2, ak = (tid & 3) * 4;
    const int bk = tid >> 4, bc = (tid & 15) * 16;

    unsigned long long acc[8][4];
#pragma unroll
    for (int p = 0; p < 8; p++)
#pragma unroll
        for (int c = 0; c < 4; c++) acc[p][c] = 0ull;

    float4 pa = *(const float4*)(A + ar * NH + ak);
    float4 pb[4];
#pragma unroll
    for (int j = 0; j < 4; j++)
        pb[j] = *(const float4*)(B + (size_t)bk * NV + n0 + bc + j * 4);

    for (int k0 = 0; k0 < NH; k0 += 16) {
        As[ak + 0][ar] = pa.x; As[ak + 1][ar] = pa.y;
        As[ak + 2][ar] = pa.z; As[ak + 3][ar] = pa.w;
#pragma unroll
        for (int j = 0; j < 4; j++)
            *(float4*)&Bs[bk][bc + j * 4] = pb[j];
        __syncthreads();
        if (k0 + 16 < NH) {
            pa = *(const float4*)(A + ar * NH + k0 + 16 + ak);
#pragma unroll
            for (int j = 0; j < 4; j++)
                pb[j] = *(const float4*)(B + (size_t)(k0 + 16 + bk) * NV + n0 + bc + j * 4);
        }
#pragma unroll
        for (int k = 0; k < 16; k++) {
            ulonglong2 pAB = *(const ulonglong2*)&As[k][rowg * 16];
            ulonglong2 pCD = *(const ulonglong2*)&As[k][rowg * 16 + 4];
            ulonglong2 pEF = *(const ulonglong2*)&As[k][rowg * 16 + 8];
            ulonglong2 pGH = *(const ulonglong2*)&As[k][rowg * 16 + 12];
            float4 bv = *(const float4*)&Bs[k][colg * 4];
            unsigned long long b0 = pk2(bv.x), b1 = pk2(bv.y);
            unsigned long long b2 = pk2(bv.z), b3 = pk2(bv.w);
            fma2(acc[0][0], pAB.x, b0); fma2(acc[0][1], pAB.x, b1);
            fma2(acc[0][2], pAB.x, b2); fma2(acc[0][3], pAB.x, b3);
            fma2(acc[1][0], pAB.y, b0); fma2(acc[1][1], pAB.y, b1);
            fma2(acc[1][2], pAB.y, b2); fma2(acc[1][3], pAB.y, b3);
            fma2(acc[2][0], pCD.x, b0); fma2(acc[2][1], pCD.x, b1);
            fma2(acc[2][2], pCD.x, b2); fma2(acc[2][3], pCD.x, b3);
            fma2(acc[3][0], pCD.y, b0); fma2(acc[3][1], pCD.y, b1);
            fma2(acc[3][2], pCD.y, b2); fma2(acc[3][3], pCD.y, b3);
            fma2(acc[4][0], pEF.x, b0); fma2(acc[4][1], pEF.x, b1);
            fma2(acc[4][2], pEF.x, b2); fma2(acc[4][3], pEF.x, b3);
            fma2(acc[5][0], pEF.y, b0); fma2(acc[5][1], pEF.y, b1);
            fma2(acc[5][2], pEF.y, b2); fma2(acc[5][3], pEF.y, b3);
            fma2(acc[6][0], pGH.x, b0); fma2(acc[6][1], pGH.x, b1);
            fma2(acc[6][2], pGH.x, b2); fma2(acc[6][3], pGH.x, b3);
            fma2(acc[7][0], pGH.y, b0); fma2(acc[7][1], pGH.y, b1);
            fma2(acc[7][2], pGH.y, b2); fma2(acc[7][3], pGH.y, b3);
        }
        __syncthreads();
    }

    // ---- epilogue: softmax partials + two-pass gumbel argmax ----
    float bcol[4];
#pragma unroll
    for (int c = 0; c < 4; c++) bcol[c] = bias[n0 + colg * 4 + c];
    uint32_t kk0, kk1;
    tf2x32(0u, 1234u, 0u, (uint32_t)t, kk0, kk1);   // fold_in(key(1234), t)

    for (int i = 0; i < 16; i++) {
        int p = i >> 1;
        int rowAbs = rowg * 16 + i;
        float m = negInf(), S = 0.f, T = 0.f;

        // pass A: approx scores (tail exact), thread-local row max
        float ll[4], uu[4], sv[4];
        uint32_t approxMask = 0;
        float rb = negInf();
#pragma unroll
        for (int c = 0; c < 4; c++) {
            float l = __fadd_rn((i & 1) ? hi32(acc[p][c]) : lo32(acc[p][c]), bcol[c]);
            ll[c] = l;
            if (S == 0.f) { m = l; S = 1.f; T = 0.f; }
            else if (l > m) {
                float e = expf(m - l);
                T = (T + (m - l) * S) * e;
                S = S * e + 1.f;
                m = l;
            } else {
                float d = l - m, e = expf(d);
                S += e; T += d * e;
            }
            int v = n0 + colg * 4 + c;
            uint32_t o0, o1;
            tf2x32(kk0, kk1, 0u, (uint32_t)(rowAbs * NV + v), o0, o1);
            float u = u01(o0 ^ o1);
            uu[c] = u;
            float af = -__logf(u);
            float s;
            if (af < 1e-4f) {
                s = __fadd_rn(l, exact_g(u));       // exact now (tail, likely winner)
            } else {
                s = l - __logf(af);                 // fast approx
                approxMask |= (1u << c);
            }
            sv[c] = s;
            rb = fmaxf(rb, s);
        }
        for (int o = 16; o; o >>= 1)
            rb = fmaxf(rb, __shfl_xor_sync(0xffffffffu, rb, o));
        if (lane == 0) red[w][6] = rb;
        __syncthreads();
        rb = fmaxf(rb, red[w ^ 1][6]);
        float thresh = rb - 4e-3f;

        // pass B: exact-evaluate only margin survivors
        float best = negInf(), bl = 0.f;
        int bidx = 0x7fffffff;
#pragma unroll
        for (int c = 0; c < 4; c++) {
            float s;
            if (approxMask & (1u << c)) {
                if (sv[c] < thresh) continue;
                s = __fadd_rn(ll[c], exact_g(uu[c]));
            } else {
                s = sv[c];
                if (s < thresh) continue;
            }
            int v = n0 + colg * 4 + c;
            if (s > best || (s == best && v < bidx)) { best = s; bidx = v; bl = ll[c]; }
        }
        for (int o = 16; o; o >>= 1) {
            float m2 = __shfl_down_sync(0xffffffffu, m, o);
            float S2 = __shfl_down_sync(0xffffffffu, S, o);
            float T2 = __shfl_down_sync(0xffffffffu, T, o);
            softmerge(m, S, T, m2, S2, T2);
            float v2 = __shfl_down_sync(0xffffffffu, best, o);
            int   i2 = __shfl_down_sync(0xffffffffu, bidx, o);
            float l2 = __shfl_down_sync(0xffffffffu, bl, o);
            if (v2 > best || (v2 == best && i2 < bidx)) { best = v2; bidx = i2; bl = l2; }
        }
        __syncthreads();
        if (lane == 0) {
            red[w][0] = m; red[w][1] = S; red[w][2] = T;
            red[w][3] = best; red[w][4] = __int_as_float(bidx); red[w][5] = bl;
        }
        __syncthreads();
        if ((w & 1) == 0 && lane == 0) {
            softmerge(m, S, T, red[w + 1][0], red[w + 1][1], red[w + 1][2]);
            float v2 = red[w + 1][3]; int i2 = __float_as_int(red[w + 1][4]);
            float l2 = red[w + 1][5];
            if (v2 > best || (v2 == best && i2 < bidx)) { best = v2; bidx = i2; bl = l2; }
            int o = (t * NBLK + blockIdx.y) * NB + rowAbs;
            g_pm[o] = make_float4(m, S, T, 0.f);
            g_pa[o] = make_float4(best, (float)bidx, bl, 0.f);
        }
        __syncthreads();
    }
}

// Final merge over the 125 block partials, all 31 steps at once.
__global__ void k_fin(float* __restrict__ out) {
    int t = blockIdx.x;
    int tid = threadIdx.x, w = tid >> 5, lane = tid & 31;
    for (int row = w; row < NB; row += 8) {
        float m = negInf(), S = 0.f, T = 0.f;
        float best = negInf(), bl = 0.f;
        int bidx = 0x7fffffff;
        for (int b = lane; b < NBLK; b += 32) {
            int o = (t * NBLK + b) * NB + row;
            float4 pm = g_pm[o];
            softmerge(m, S, T, pm.x, pm.y, pm.z);
            float4 pa = g_pa[o];
            int i2 = (int)pa.y;
            if (pa.x > best || (pa.x == best && i2 < bidx)) {
                best = pa.x; bidx = i2; bl = pa.z;
            }
        }
        for (int o = 16; o; o >>= 1) {
            float m2 = __shfl_down_sync(0xffffffffu, m, o);
            float S2 = __shfl_down_sync(0xffffffffu, S, o);
            float T2 = __shfl_down_sync(0xffffffffu, T, o);
            softmerge(m, S, T, m2, S2, T2);
            float v2 = __shfl_down_sync(0xffffffffu, best, o);
            int   i2 = __shfl_down_sync(0xffffffffu, bidx, o);
            float l2 = __shfl_down_sync(0xffffffffu, bl, o);
            if (v2 > best || (v2 == best && i2 < bidx)) { best = v2; bidx = i2; bl = l2; }
        }
        if (lane == 0) {
            float lS = (float)log((double)S);
            out[2 * NB * 2 * NT + row * (2 * NT) + t] = lS - T / S;   // entropy
            out[row * (2 * NT) + t] = (float)bidx;                    // msg
            out[NB * 2 * NT + row * (2 * NT) + t] =
                __fadd_rn(__fadd_rn(bl, -m), -lS);                    // log_prob
        }
    }
}

__global__ void k_copyh(float* __restrict__ out, const float* __restrict__ h) {
    int i = blockIdx.x * blockDim.x + threadIdx.x;
    if (i < NB * NH) out[3 * NB * 2 * NT + i] = h[i];
}

extern "C" void kernel_launch(void* const* d_in, const int* in_sizes, int n_in,
                              void* d_out, int out_size) {
    // Size-based dispatch (robust to metadata ordering):
    const float *inp = 0, *Wx1 = 0, *Wd = 0, *bd = 0, *b1 = 0, *b2 = 0;
    const float* w4[3] = {0, 0, 0};
    int n4 = 0;
    for (int i = 0; i < n_in; i++) {
        const float* p = (const float*)d_in[i];
        switch (in_sizes[i]) {
            case 32768:    inp = p; break;
            case 2097152:  Wx1 = p; break;
            case 4194304:  if (n4 < 3) w4[n4++] = p; break;   // Wh1(unused), Wx2, Wh2
            case 32768000: Wd = p; break;
            case 32000:    bd = p; break;
            case 4096:     if (!b1) b1 = p; else b2 = p; break;
            default: break;
        }
    }
    float* out = (float*)d_out;

    void *pw1, *pw2, *phs;
    cudaGetSymbolAddress(&pw1, g_W1p);
    cudaGetSymbolAddress(&pw2, g_W2p);
    cudaGetSymbolAddress(&phs, g_hs);
    float* W1p = (float*)pw1;
    float* W2p = (float*)pw2;
    float* hs  = (float*)phs;

    k_init<<<256, 256>>>();
    k_init2<<<48, 256>>>(out);
    k_prep<<<16384, 256>>>(Wx1, w4[1], w4[2]);

    // encoder: one step, zero state -> hs[0]
    gemmG<<<256, 256>>>(inp, W1p, b1, hs, 512);

    // decoder state chain (the only sequential dependency)
    for (int t = 0; t < NT; t++)
        gemmG<<<256, 256>>>(hs + (size_t)t * NB * NH, W2p, b2,
                            hs + (size_t)(t + 1) * NB * NH, NH);

    // all 31 logits+sampling GEMMs in one wave-parallel launch
    gemmF<<<dim3(NT, NBLK), 256>>>(hs, Wd, bd);

    k_fin<<<NT, 256>>>(out);
    k_copyh<<<256, 256>>>(out, hs + (size_t)NT * NB * NH);
}